// round 2
// baseline (speedup 1.0000x reference)
#include <cuda_runtime.h>
#include <cuda_bf16.h>

#define NCELLS 50000
#define NGENES 1000
#define NCLS   30
#define NOUT   8
#define NCOEF  76      // [0,30): invVar  [30,60): Mu*invVar  [60,68): Wl  [68,76): Wr
#define EMAXN  800000

// -------- scratch (device globals; no allocation allowed) --------
__device__ __align__(16) float g_Cf[NGENES * NCOEF];
__device__ float g_Dc[NCLS];
__device__ __align__(16) float g_logP[NCELLS * NCLS];
__device__ __align__(16) float g_xl[NCELLS * NOUT];
__device__ __align__(16) float g_xr[NCELLS * NOUT];
__device__ int   g_src[EMAXN];
__device__ int   g_dst[EMAXN];
__device__ float g_e[EMAXN];
__device__ float g_eexp[EMAXN];
__device__ float g_denom[NCELLS];
__device__ int   g_emax[NCELLS];
__device__ int   g_is64;
__device__ double g_ll;
__device__ double g_ce;

// ---------------- edge dtype detection ----------------
// If buffer is int64 (values < 50000), every odd 32-bit word is 0.
// If it's int32 random indices, odd words are nonzero w.h.p.
__global__ void k_detect(const int* __restrict__ ei32) {
    int is64 = 1;
    #pragma unroll
    for (int i = 1; i < 64; i += 2)
        if (ei32[i] != 0) { is64 = 0; break; }
    g_is64 = is64;
}

__global__ void k_convert(const int* __restrict__ ei32, int E) {
    int e = blockIdx.x * blockDim.x + threadIdx.x;
    if (e >= E) return;
    int s, d;
    if (g_is64) { s = ei32[2 * e]; d = ei32[2 * (E + e)]; }
    else        { s = ei32[e];     d = ei32[E + e]; }
    // defensive mask: wrong detection -> wrong answer (visible), not a crash
    g_src[e] = ((unsigned)s < NCELLS) ? s : 0;
    g_dst[e] = ((unsigned)d < NCELLS) ? d : 0;
}

// ---------------- init (graph-replay safe reset) ----------------
__global__ void k_init() {
    int i = blockIdx.x * blockDim.x + threadIdx.x;
    if (i == 0) { g_ll = 0.0; g_ce = 0.0; }
    if (i < NCELLS) {
        g_denom[i] = 0.f;
        g_emax[i]  = 0x80000000;   // below any ordered-int key of a finite float
    }
}

// ---------------- pack per-gene coefficients ----------------
__global__ void k_prep(const float* __restrict__ Mu, const float* __restrict__ Var,
                       const float* __restrict__ Wl, const float* __restrict__ Wr) {
    int g = blockIdx.x * blockDim.x + threadIdx.x;
    if (g >= NGENES) return;
    #pragma unroll
    for (int c = 0; c < NCLS; c++) {
        float iv = 1.0f / Var[c * NGENES + g];
        g_Cf[g * NCOEF + c]        = iv;
        g_Cf[g * NCOEF + 30 + c]   = Mu[c * NGENES + g] * iv;
    }
    #pragma unroll
    for (int o = 0; o < NOUT; o++) {
        g_Cf[g * NCOEF + 60 + o] = Wl[o * NGENES + g];
        g_Cf[g * NCOEF + 68 + o] = Wr[o * NGENES + g];
    }
}

// ---------------- D[c] = sum_g Mu^2/Var ----------------
__global__ void k_dc(const float* __restrict__ Mu, const float* __restrict__ Var) {
    int c = blockIdx.x, t = threadIdx.x;
    float s = 0.f;
    for (int g = t; g < NGENES; g += blockDim.x) {
        float mu = Mu[c * NGENES + g];
        s += mu * mu / Var[c * NGENES + g];
    }
    __shared__ float sh[256];
    sh[t] = s; __syncthreads();
    for (int o = 128; o; o >>= 1) { if (t < o) sh[t] += sh[t + o]; __syncthreads(); }
    if (t == 0) g_Dc[c] = sh[0];
}

// ---------------- row softmax: P and log(P+1e-8) ----------------
__global__ void k_softmax(const float* __restrict__ W, float* __restrict__ Pout) {
    int warp = (blockIdx.x * blockDim.x + threadIdx.x) >> 5;
    int lane = threadIdx.x & 31;
    int nw   = (gridDim.x * blockDim.x) >> 5;
    for (int i = warp; i < NCELLS; i += nw) {
        float w = (lane < NCLS) ? W[i * NCLS + lane] : -3.4e38f;
        float m = w;
        #pragma unroll
        for (int o = 16; o; o >>= 1) m = fmaxf(m, __shfl_xor_sync(~0u, m, o));
        float e = (lane < NCLS) ? expf(w - m) : 0.f;
        float s = e;
        #pragma unroll
        for (int o = 16; o; o >>= 1) s += __shfl_xor_sync(~0u, s, o);
        float p = e / s;
        if (lane < NCLS) {
            Pout[i * NCLS + lane]   = p;
            g_logP[i * NCLS + lane] = logf(p + 1e-8f);
        }
    }
}

// ---------------- fused X scan: ll_prot partial + x_l/x_r ----------------
#define GT  40           // gene tile (divides 1000)
#define CPB 128          // cells per block
#define XPAD (GT + 1)    // stride 41: conflict-free column reads

__global__ __launch_bounds__(CPB) void k_main(const float* __restrict__ X,
                                              const float* __restrict__ S,
                                              const float* __restrict__ Pout,
                                              const float* __restrict__ bl,
                                              const float* __restrict__ br) {
    __shared__ float xs[CPB * XPAD];
    __shared__ float cf[GT * NCOEF];
    __shared__ float red[CPB];

    const int t     = threadIdx.x;
    const int cell0 = blockIdx.x * CPB;
    const int cell  = cell0 + t;

    float accA[NCLS], accB[NCLS], xl[NOUT], xr[NOUT];
    #pragma unroll
    for (int c = 0; c < NCLS; c++) { accA[c] = 0.f; accB[c] = 0.f; }
    #pragma unroll
    for (int o = 0; o < NOUT; o++) { xl[o] = 0.f; xr[o] = 0.f; }

    for (int g0 = 0; g0 < NGENES; g0 += GT) {
        // stage X tile (coalesced: consecutive threads -> consecutive genes)
        for (int idx = t; idx < CPB * GT; idx += CPB) {
            int r = idx / GT, gi = idx % GT;
            int cc = cell0 + r;
            xs[r * XPAD + gi] = (cc < NCELLS) ? X[cc * NGENES + g0 + gi] : 0.f;
        }
        // stage coefficient tile (contiguous)
        for (int idx = t; idx < GT * NCOEF; idx += CPB)
            cf[idx] = g_Cf[g0 * NCOEF + idx];
        __syncthreads();

        #pragma unroll 2
        for (int g = 0; g < GT; g++) {
            float x  = xs[t * XPAD + g];
            float x2 = x * x;
            const float* cg = &cf[g * NCOEF];
            #pragma unroll
            for (int c = 0; c < NCLS; c++) accA[c] = fmaf(x2, cg[c],      accA[c]);
            #pragma unroll
            for (int c = 0; c < NCLS; c++) accB[c] = fmaf(x,  cg[30 + c], accB[c]);
            #pragma unroll
            for (int o = 0; o < NOUT; o++) xl[o]   = fmaf(x,  cg[60 + o], xl[o]);
            #pragma unroll
            for (int o = 0; o < NOUT; o++) xr[o]   = fmaf(x,  cg[68 + o], xr[o]);
        }
        __syncthreads();
    }

    float fdot = 0.f;
    if (cell < NCELLS) {
        float s1 = S[cell];
        float s2 = s1 * s1;
        #pragma unroll
        for (int c = 0; c < NCLS; c++) {
            float F = -0.5f * (accA[c] - 2.f * s1 * accB[c] + s2 * g_Dc[c]);
            fdot = fmaf(Pout[cell * NCLS + c], F, fdot);
        }
        #pragma unroll
        for (int o = 0; o < NOUT; o++) {
            g_xl[cell * NOUT + o] = xl[o] + bl[o];
            g_xr[cell * NOUT + o] = xr[o] + br[o];
        }
    }
    red[t] = fdot; __syncthreads();
    for (int o = CPB / 2; o; o >>= 1) { if (t < o) red[t] += red[t + o]; __syncthreads(); }
    if (t == 0) atomicAdd(&g_ll, (double)red[0]);
}

// ---------------- edge pass 1: scores + segment max ----------------
__device__ __forceinline__ int f2ord(float f) {
    int i = __float_as_int(f);
    return (i >= 0) ? i : (i ^ 0x7fffffff);
}
__device__ __forceinline__ float ord2f(int k) {
    return __int_as_float((k >= 0) ? k : (k ^ 0x7fffffff));
}

__global__ void k_edge1(const float* __restrict__ att, int E) {
    int e = blockIdx.x * blockDim.x + threadIdx.x;
    if (e >= E) return;
    int s = g_src[e];
    int d = g_dst[e];
    float4 a0 = *(const float4*)&g_xl[s * NOUT];
    float4 a1 = *(const float4*)&g_xl[s * NOUT + 4];
    float4 b0 = *(const float4*)&g_xr[d * NOUT];
    float4 b1 = *(const float4*)&g_xr[d * NOUT + 4];
    float m[8] = { a0.x + b0.x, a0.y + b0.y, a0.z + b0.z, a0.w + b0.w,
                   a1.x + b1.x, a1.y + b1.y, a1.z + b1.z, a1.w + b1.w };
    float ev = 0.f;
    #pragma unroll
    for (int o = 0; o < NOUT; o++) {
        float v = m[o];
        v = (v > 0.f) ? v : 0.2f * v;        // leaky_relu, slope 0.2
        ev = fmaf(v, __ldg(&att[o]), ev);
    }
    g_e[e] = ev;
    atomicMax(&g_emax[d], f2ord(ev));
}

// ---------------- edge pass 2: exp + segment sum ----------------
__global__ void k_edge2(int E) {
    int e = blockIdx.x * blockDim.x + threadIdx.x;
    if (e >= E) return;
    int d = g_dst[e];
    float ex = expf(g_e[e] - ord2f(g_emax[d]));
    g_eexp[e] = ex;
    atomicAdd(&g_denom[d], ex);
}

// ---------------- edge pass 3: cross-entropy (warp per edge) ----------------
__global__ void k_edge3(const float* __restrict__ Pout, int E) {
    int gw   = (blockIdx.x * blockDim.x + threadIdx.x) >> 5;
    int lane = threadIdx.x & 31;
    int nw   = (gridDim.x * blockDim.x) >> 5;
    float acc = 0.f;
    for (int e = gw; e < E; e += nw) {
        int s = g_src[e];
        int d = g_dst[e];
        float alpha = g_eexp[e] / (g_denom[d] + 1e-16f);
        float v = (lane < NCLS) ? Pout[s * NCLS + lane] * g_logP[d * NCLS + lane] : 0.f;
        #pragma unroll
        for (int o = 16; o; o >>= 1) v += __shfl_xor_sync(~0u, v, o);
        if (lane == 0) acc = fmaf(alpha, v, acc);
    }
    if (lane == 0) atomicAdd(&g_ce, (double)acc);
}

// ---------------- finalize scalars ----------------
__global__ void k_final(float* out) {
    out[0] = (float)(g_ll / (double)NCELLS);
    out[1] = (float)(-g_ce / (double)NCELLS);
}

extern "C" void kernel_launch(void* const* d_in, const int* in_sizes, int n_in,
                              void* d_out, int out_size) {
    const float* X   = (const float*)d_in[0];
    const float* Mu  = (const float*)d_in[1];
    const float* Var = (const float*)d_in[2];
    const int*   ei  = (const int*)d_in[3];
    const float* W   = (const float*)d_in[4];
    const float* S   = (const float*)d_in[5];
    const float* Wl  = (const float*)d_in[6];
    const float* bl  = (const float*)d_in[7];
    const float* Wr  = (const float*)d_in[8];
    const float* br  = (const float*)d_in[9];
    const float* att = (const float*)d_in[10];
    float* out = (float*)d_out;
    int E = in_sizes[3] / 2;
    if (E > EMAXN) E = EMAXN;

    k_detect <<<1, 1>>>(ei);
    k_convert<<<(E + 255) / 256, 256>>>(ei, E);
    k_init   <<<(NCELLS + 255) / 256, 256>>>();
    k_prep   <<<(NGENES + 127) / 128, 128>>>(Mu, Var, Wl, Wr);
    k_dc     <<<NCLS, 256>>>(Mu, Var);
    k_softmax<<<256, 256>>>(W, out + 2);
    k_main   <<<(NCELLS + CPB - 1) / CPB, CPB>>>(X, S, out + 2, bl, br);
    k_edge1  <<<(E + 255) / 256, 256>>>(att, E);
    k_edge2  <<<(E + 255) / 256, 256>>>(E);
    k_edge3  <<<1024, 256>>>(out + 2, E);
    k_final  <<<1, 1>>>(out);
}